// round 1
// baseline (speedup 1.0000x reference)
#include <cuda_runtime.h>
#include <cstdint>

#define N_TOK 8192
#define D_IN  1024
#define D_OUTP 1024
#define NE    8
#define K_TOT (NE * D_IN)      // 8192

#define BM 128
#define BN 128
#define BK 32
#define AS_STRIDE 36           // BK + 4  -> A frag loads conflict-free
#define BS_STRIDE 136          // BN + 8  -> stride%32==8 -> B frag loads conflict-free
#define SMEM_FLOATS (2 * BM * AS_STRIDE + 2 * BK * BS_STRIDE)
#define SMEM_BYTES  (SMEM_FLOATS * 4)   // 71680

// Scratch (allocation-free): tf32-rounded copies + gate weights
__device__ float g_xr[(size_t)N_TOK * D_IN];
__device__ float g_Wr[(size_t)K_TOT * D_OUTP];
__device__ float g_gate[N_TOK * NE];

__device__ __forceinline__ float tf32_rna(float x) {
    uint32_t u;
    asm("cvt.rna.tf32.f32 %0, %1;" : "=r"(u) : "f"(x));
    return __uint_as_float(u);
}

// -------------------------------------------------------------------------
// Prepass: round fp32 -> tf32 (round-to-nearest) into scratch
// which = 0: x -> g_xr ; which = 1: We -> g_Wr
// -------------------------------------------------------------------------
__global__ void round_kernel(const float* __restrict__ src, int which, int n4) {
    int i = blockIdx.x * blockDim.x + threadIdx.x;
    if (i >= n4) return;
    float4 v = reinterpret_cast<const float4*>(src)[i];
    v.x = tf32_rna(v.x);
    v.y = tf32_rna(v.y);
    v.z = tf32_rna(v.z);
    v.w = tf32_rna(v.w);
    float4* dst = which == 0 ? reinterpret_cast<float4*>(g_xr)
                             : reinterpret_cast<float4*>(g_Wr);
    dst[i] = v;
}

// -------------------------------------------------------------------------
// Gate: softmax(x @ Wg + bg) over E=8, one warp per token
// -------------------------------------------------------------------------
__global__ __launch_bounds__(256) void gate_kernel(const float* __restrict__ x,
                                                   const float* __restrict__ Wg,
                                                   const float* __restrict__ bg) {
    __shared__ float sWg[NE][D_IN];   // transposed: [e][i], conflict-free reads
    int tid = threadIdx.x;
    for (int idx = tid; idx < D_IN * NE; idx += 256) {
        int i = idx >> 3, e = idx & 7;
        sWg[e][i] = Wg[idx];
    }
    __syncthreads();

    int warp = tid >> 5, lane = tid & 31;
    int n = blockIdx.x * 8 + warp;
    const float* xr = x + (size_t)n * D_IN;

    float acc[NE];
#pragma unroll
    for (int e = 0; e < NE; e++) acc[e] = 0.f;
    for (int i = lane; i < D_IN; i += 32) {
        float xv = xr[i];
#pragma unroll
        for (int e = 0; e < NE; e++) acc[e] += xv * sWg[e][i];
    }
#pragma unroll
    for (int e = 0; e < NE; e++) {
#pragma unroll
        for (int off = 16; off; off >>= 1)
            acc[e] += __shfl_xor_sync(0xffffffffu, acc[e], off);
    }
    if (lane == 0) {
        float m = -1e30f;
#pragma unroll
        for (int e = 0; e < NE; e++) { acc[e] += bg[e]; m = fmaxf(m, acc[e]); }
        float s = 0.f;
#pragma unroll
        for (int e = 0; e < NE; e++) { acc[e] = expf(acc[e] - m); s += acc[e]; }
        float inv = 1.f / s;
#pragma unroll
        for (int e = 0; e < NE; e++) g_gate[n * NE + e] = acc[e] * inv;
    }
}

// -------------------------------------------------------------------------
// Main fused GEMM: out = A'(gate-scaled x) @ We' + gate @ be
// Implemented as one [8192 x 8192 x 1024] tf32 GEMM with per-expert register
// fold (acc_tot += g_e * (acc_part + be)) every 32 k-tiles.
// -------------------------------------------------------------------------
__device__ __forceinline__ void cp_async16(uint32_t saddr, const void* gptr) {
    asm volatile("cp.async.cg.shared.global [%0], [%1], 16;\n"
                 :: "r"(saddr), "l"(gptr));
}
__device__ __forceinline__ void cp_commit() {
    asm volatile("cp.async.commit_group;\n");
}
template <int n> __device__ __forceinline__ void cp_wait() {
    asm volatile("cp.async.wait_group %0;\n" :: "n"(n));
}

__device__ __forceinline__ void mma_tf32(float c[4], const uint32_t a[4],
                                         uint32_t b0, uint32_t b1) {
    asm volatile(
        "mma.sync.aligned.m16n8k8.row.col.f32.tf32.tf32.f32 "
        "{%0,%1,%2,%3}, {%4,%5,%6,%7}, {%8,%9}, {%0,%1,%2,%3};"
        : "+f"(c[0]), "+f"(c[1]), "+f"(c[2]), "+f"(c[3])
        : "r"(a[0]), "r"(a[1]), "r"(a[2]), "r"(a[3]), "r"(b0), "r"(b1));
}

__device__ __forceinline__ void load_tiles(int kt, int buf, int n0, int o0,
                                           uint32_t as_base, uint32_t bs_base,
                                           int tid) {
    // A tile: 128 rows x 32 cols of g_xr (k-contiguous in global)
    int i0 = (kt & 31) * BK;   // column within expert's x block
#pragma unroll
    for (int j = 0; j < 4; j++) {
        int c   = tid + 256 * j;     // 0..1023
        int row = c >> 3;            // 0..127
        int c16 = c & 7;             // 0..7  (16B chunks)
        const float* src = g_xr + (size_t)(n0 + row) * D_IN + i0 + c16 * 4;
        uint32_t dst = as_base + (uint32_t)(buf * (BM * AS_STRIDE) +
                                            row * AS_STRIDE + c16 * 4) * 4u;
        cp_async16(dst, src);
    }
    // B tile: 32 k-rows x 128 o-cols of g_Wr (o-contiguous in global)
    int k0 = kt * BK;
#pragma unroll
    for (int j = 0; j < 4; j++) {
        int c    = tid + 256 * j;    // 0..1023
        int krow = c >> 5;           // 0..31
        int c16  = c & 31;           // 0..31
        const float* src = g_Wr + (size_t)(k0 + krow) * D_OUTP + o0 + c16 * 4;
        uint32_t dst = bs_base + (uint32_t)(2 * BM * AS_STRIDE +
                                            buf * (BK * BS_STRIDE) +
                                            krow * BS_STRIDE + c16 * 4) * 4u;
        cp_async16(dst, src);
    }
}

__global__ __launch_bounds__(256, 1) void moe_gemm_kernel(
    const float* __restrict__ be, float* __restrict__ out) {
    extern __shared__ float smem[];
    const int tid  = threadIdx.x;
    const int warp = tid >> 5, lane = tid & 31;
    const int gid  = lane >> 2, tid4 = lane & 3;
    const int wm   = warp >> 1, wn = warp & 1;     // 4 (m) x 2 (n) warps
    const int n0   = blockIdx.y * BM;
    const int o0   = blockIdx.x * BN;

    uint32_t smem_u32 = (uint32_t)__cvta_generic_to_shared(smem);
    const float* As = smem;
    const float* Bs = smem + 2 * BM * AS_STRIDE;

    float acc_t[2][8][4];   // total (gate-weighted) accumulators
    float acc_p[2][8][4];   // per-expert partial accumulators
#pragma unroll
    for (int mt = 0; mt < 2; mt++)
#pragma unroll
        for (int nt = 0; nt < 8; nt++)
#pragma unroll
            for (int f = 0; f < 4; f++) { acc_t[mt][nt][f] = 0.f; acc_p[mt][nt][f] = 0.f; }

    load_tiles(0, 0, n0, o0, smem_u32, smem_u32, tid);
    cp_commit();

    const int NIT = K_TOT / BK;   // 256
    for (int kt = 0; kt < NIT; kt++) {
        int buf = kt & 1;
        if (kt + 1 < NIT) load_tiles(kt + 1, buf ^ 1, n0, o0, smem_u32, smem_u32, tid);
        cp_commit();
        cp_wait<1>();
        __syncthreads();

        const float* A = As + buf * (BM * AS_STRIDE);
        const float* B = Bs + buf * (BK * BS_STRIDE);

#pragma unroll
        for (int ks = 0; ks < 4; ks++) {
            const int kk = ks * 8;
            uint32_t a[2][4];
#pragma unroll
            for (int mt = 0; mt < 2; mt++) {
                const float* Arow = A + (wm * 32 + mt * 16 + gid) * AS_STRIDE;
                a[mt][0] = __float_as_uint(Arow[kk + tid4]);
                a[mt][1] = __float_as_uint(Arow[8 * AS_STRIDE + kk + tid4]);
                a[mt][2] = __float_as_uint(Arow[kk + tid4 + 4]);
                a[mt][3] = __float_as_uint(Arow[8 * AS_STRIDE + kk + tid4 + 4]);
            }
#pragma unroll
            for (int nt = 0; nt < 8; nt++) {
                const int n = wn * 64 + nt * 8 + gid;
                uint32_t b0 = __float_as_uint(B[(kk + tid4) * BS_STRIDE + n]);
                uint32_t b1 = __float_as_uint(B[(kk + tid4 + 4) * BS_STRIDE + n]);
#pragma unroll
                for (int mt = 0; mt < 2; mt++)
                    mma_tf32(acc_p[mt][nt], a[mt], b0, b1);
            }
        }
        __syncthreads();   // protect buf before it is refilled next iteration

        // Expert boundary: fold partials with gate weight + bias
        if ((kt & 31) == 31) {
            const int e = kt >> 5;
            float gr[2][2];
#pragma unroll
            for (int mt = 0; mt < 2; mt++) {
                int rbase = n0 + wm * 32 + mt * 16 + gid;
                gr[mt][0] = g_gate[rbase * NE + e];
                gr[mt][1] = g_gate[(rbase + 8) * NE + e];
            }
#pragma unroll
            for (int nt = 0; nt < 8; nt++) {
                int col = o0 + wn * 64 + nt * 8 + 2 * tid4;
                float be0 = be[e * D_OUTP + col];
                float be1 = be[e * D_OUTP + col + 1];
#pragma unroll
                for (int mt = 0; mt < 2; mt++) {
                    acc_t[mt][nt][0] += gr[mt][0] * (acc_p[mt][nt][0] + be0);
                    acc_t[mt][nt][1] += gr[mt][0] * (acc_p[mt][nt][1] + be1);
                    acc_t[mt][nt][2] += gr[mt][1] * (acc_p[mt][nt][2] + be0);
                    acc_t[mt][nt][3] += gr[mt][1] * (acc_p[mt][nt][3] + be1);
                    acc_p[mt][nt][0] = 0.f; acc_p[mt][nt][1] = 0.f;
                    acc_p[mt][nt][2] = 0.f; acc_p[mt][nt][3] = 0.f;
                }
            }
        }
    }

    // Epilogue: write out
#pragma unroll
    for (int mt = 0; mt < 2; mt++) {
        int r0 = n0 + wm * 32 + mt * 16 + gid;
#pragma unroll
        for (int nt = 0; nt < 8; nt++) {
            int col = o0 + wn * 64 + nt * 8 + 2 * tid4;
            float2 v0 = make_float2(acc_t[mt][nt][0], acc_t[mt][nt][1]);
            float2 v1 = make_float2(acc_t[mt][nt][2], acc_t[mt][nt][3]);
            *reinterpret_cast<float2*>(out + (size_t)r0 * D_OUTP + col) = v0;
            *reinterpret_cast<float2*>(out + (size_t)(r0 + 8) * D_OUTP + col) = v1;
        }
    }
}

// -------------------------------------------------------------------------
extern "C" void kernel_launch(void* const* d_in, const int* in_sizes, int n_in,
                              void* d_out, int out_size) {
    const float* x  = (const float*)d_in[0];
    const float* We = (const float*)d_in[1];
    const float* be = (const float*)d_in[2];
    const float* Wg = (const float*)d_in[3];
    const float* bg = (const float*)d_in[4];
    float* out = (float*)d_out;

    cudaFuncSetAttribute(moe_gemm_kernel,
                         cudaFuncAttributeMaxDynamicSharedMemorySize, SMEM_BYTES);

    const int n4 = (N_TOK * D_IN) / 4;   // 2,097,152 float4 (same for x and We)
    round_kernel<<<(n4 + 255) / 256, 256>>>(x, 0, n4);
    round_kernel<<<(n4 + 255) / 256, 256>>>(We, 1, n4);
    gate_kernel<<<N_TOK / 8, 256>>>(x, Wg, bg);

    dim3 grid(D_OUTP / BN, N_TOK / BM);   // (8, 64)
    moe_gemm_kernel<<<grid, 256, SMEM_BYTES>>>(be, out);
}

// round 7
// speedup vs baseline: 2.1858x; 2.1858x over previous
#include <cuda_runtime.h>
#include <cuda_fp16.h>
#include <cstdint>

#define N_TOK 8192
#define D_IN  1024
#define D_OUTV 1024
#define NE    8
#define K_TOT 8192
#define K_PAD 8256            // 8192 + 64 (bias fold + zero pad), 129 * 64

#define BM 128
#define BN 256
#define BK 64
#define STAGES 3
#define NIT (K_PAD / BK)      // 129
#define THREADS 256

#define A_STAGE (BM * BK * 2)         // 16384
#define B_STAGE (BN * BK * 2)         // 32768
#define SMEM_BYTES (STAGES * (A_STAGE + B_STAGE))   // 147456

// ---- scratch (allocation-free device globals) ----
__device__ __align__(1024) __half g_Ah[(size_t)N_TOK * K_PAD];   // A' = gate-scaled x + gate cols
__device__ __align__(1024) __half g_Bh[(size_t)D_OUTV * K_PAD];  // W' [o][k] + bias cols
__device__ float g_gate[N_TOK * NE];

// ============================ PTX helpers ============================
__device__ __forceinline__ uint32_t smem_u32(const void* p) {
    uint32_t a;
    asm("{ .reg .u64 t; cvta.to.shared.u64 t, %1; cvt.u32.u64 %0, t; }" : "=r"(a) : "l"(p));
    return a;
}
__device__ __forceinline__ void cp_async16(uint32_t saddr, const void* gptr) {
    asm volatile("cp.async.cg.shared.global [%0], [%1], 16;\n" :: "r"(saddr), "l"(gptr));
}
__device__ __forceinline__ void cp_commit() {
    asm volatile("cp.async.commit_group;\n");
}
template <int n> __device__ __forceinline__ void cp_wait() {
    asm volatile("cp.async.wait_group %0;\n" :: "n"(n));
}
__device__ __forceinline__ void ldsm4(uint32_t r[4], uint32_t addr) {
    asm volatile("ldmatrix.sync.aligned.m8n8.x4.shared.b16 {%0,%1,%2,%3}, [%4];"
                 : "=r"(r[0]), "=r"(r[1]), "=r"(r[2]), "=r"(r[3]) : "r"(addr));
}
__device__ __forceinline__ void mma16816(float c[4], const uint32_t a[4],
                                         uint32_t b0, uint32_t b1) {
    asm volatile(
        "mma.sync.aligned.m16n8k16.row.col.f32.f16.f16.f32 "
        "{%0,%1,%2,%3}, {%4,%5,%6,%7}, {%8,%9}, {%0,%1,%2,%3};"
        : "+f"(c[0]), "+f"(c[1]), "+f"(c[2]), "+f"(c[3])
        : "r"(a[0]), "r"(a[1]), "r"(a[2]), "r"(a[3]), "r"(b0), "r"(b1));
}

// ============================ prepass kernels ============================
__global__ __launch_bounds__(256) void gate_kernel(const float* __restrict__ x,
                                                   const float* __restrict__ Wg,
                                                   const float* __restrict__ bg) {
    __shared__ float sWg[NE][D_IN];
    int tid = threadIdx.x;
    for (int idx = tid; idx < D_IN * NE; idx += 256) {
        int i = idx >> 3, e = idx & 7;
        sWg[e][i] = Wg[idx];
    }
    __syncthreads();
    int warp = tid >> 5, lane = tid & 31;
    int n = blockIdx.x * 8 + warp;
    const float* xr = x + (size_t)n * D_IN;
    float acc[NE];
#pragma unroll
    for (int e = 0; e < NE; e++) acc[e] = 0.f;
    for (int i = lane; i < D_IN; i += 32) {
        float xv = xr[i];
#pragma unroll
        for (int e = 0; e < NE; e++) acc[e] += xv * sWg[e][i];
    }
#pragma unroll
    for (int e = 0; e < NE; e++)
#pragma unroll
        for (int off = 16; off; off >>= 1)
            acc[e] += __shfl_xor_sync(0xffffffffu, acc[e], off);
    if (lane == 0) {
        float m = -1e30f;
#pragma unroll
        for (int e = 0; e < NE; e++) { acc[e] += bg[e]; m = fmaxf(m, acc[e]); }
        float s = 0.f;
#pragma unroll
        for (int e = 0; e < NE; e++) { acc[e] = expf(acc[e] - m); s += acc[e]; }
        float inv = 1.f / s;
#pragma unroll
        for (int e = 0; e < NE; e++) g_gate[n * NE + e] = acc[e] * inv;
    }
}

// A'[n][e*1024+i] = fp16(g_e * x[n,i]); cols 8192+e = g_e; pad zeros to 8255
__global__ __launch_bounds__(512) void prescale_kernel(const float* __restrict__ x) {
    __shared__ float g[NE];
    int n = blockIdx.x, t = threadIdx.x;
    if (t < NE) g[t] = g_gate[n * NE + t];
    __syncthreads();
    float2 v = reinterpret_cast<const float2*>(x + (size_t)n * D_IN)[t];
    __half* dst = g_Ah + (size_t)n * K_PAD;
#pragma unroll
    for (int e = 0; e < NE; e++) {
        __half2 h = __floats2half2_rn(g[e] * v.x, g[e] * v.y);
        reinterpret_cast<__half2*>(dst + e * D_IN)[t] = h;
    }
    if (t < 32) {   // K extension: 64 cols = 32 half2
        __half2 h = (t < 4) ? __floats2half2_rn(g[2 * t], g[2 * t + 1])
                            : __floats2half2_rn(0.f, 0.f);
        reinterpret_cast<__half2*>(dst + K_TOT)[t] = h;
    }
}

// W'[o][e*1024+i] = fp16(We[e][i][o]) — tiled transpose
__global__ __launch_bounds__(256) void transW_kernel(const float* __restrict__ We) {
    __shared__ float t[32][33];
    int e = blockIdx.z;
    int i0 = blockIdx.y * 32, o0 = blockIdx.x * 32;
    int tx = threadIdx.x, ty = threadIdx.y;
    for (int r = ty; r < 32; r += 8)
        t[r][tx] = We[((size_t)e * D_IN + i0 + r) * D_OUTV + o0 + tx];
    __syncthreads();
    for (int r = ty; r < 32; r += 8)
        g_Bh[(size_t)(o0 + r) * K_PAD + e * D_IN + i0 + tx] = __float2half(t[tx][r]);
}

// B' bias cols: [o][8192+e] = be[e][o], zeros to 8255
__global__ __launch_bounds__(256) void biasB_kernel(const float* __restrict__ be) {
    int idx = blockIdx.x * 256 + threadIdx.x;   // 0 .. 32767
    int o = idx >> 5, j = idx & 31;
    __half2 h = (j < 4) ? __floats2half2_rn(be[(2 * j) * D_OUTV + o],
                                            be[(2 * j + 1) * D_OUTV + o])
                        : __floats2half2_rn(0.f, 0.f);
    reinterpret_cast<__half2*>(g_Bh + (size_t)o * K_PAD + K_TOT)[j] = h;
}

// ============================ main GEMM ============================
__device__ __forceinline__ void load_stage(int kt, int s, int m0, int o0,
                                           uint32_t sA, uint32_t sB, int tid) {
    const int k0 = kt * BK;
#pragma unroll
    for (int j = 0; j < 4; j++) {            // A: 128 rows x 8 chunks
        int idx = j * 256 + tid;
        int r = idx >> 3, c = idx & 7;
        const void* src = g_Ah + (size_t)(m0 + r) * K_PAD + k0 + c * 8;
        cp_async16(sA + s * A_STAGE + r * 128 + ((c ^ (r & 7)) << 4), src);
    }
#pragma unroll
    for (int j = 0; j < 8; j++) {            // B: 256 rows x 8 chunks
        int idx = j * 256 + tid;
        int r = idx >> 3, c = idx & 7;
        const void* src = g_Bh + (size_t)(o0 + r) * K_PAD + k0 + c * 8;
        cp_async16(sB + s * B_STAGE + r * 128 + ((c ^ (r & 7)) << 4), src);
    }
}

__global__ __launch_bounds__(THREADS, 1) void moe_gemm_kernel(float* __restrict__ out) {
    extern __shared__ char smem[];
    const uint32_t sA = smem_u32(smem);
    const uint32_t sB = sA + STAGES * A_STAGE;
    const int tid = threadIdx.x, warp = tid >> 5, lane = tid & 31;
    const int wm = warp & 1, wn = warp >> 1;          // 2 (m) x 4 (n)
    const int m0 = blockIdx.y * BM;
    const int o0 = blockIdx.x * BN;
    const int lr = lane & 15, lc = lane >> 4;

    float acc[4][8][4];
#pragma unroll
    for (int mt = 0; mt < 4; mt++)
#pragma unroll
        for (int nt = 0; nt < 8; nt++)
#pragma unroll
            for (int f = 0; f < 4; f++) acc[mt][nt][f] = 0.f;

    load_stage(0, 0, m0, o0, sA, sB, tid); cp_commit();
    load_stage(1, 1, m0, o0, sA, sB, tid); cp_commit();

    int s = 0;
    for (int kt = 0; kt < NIT; kt++) {
        cp_wait<1>();
        __syncthreads();
        if (kt + 2 < NIT) {
            int s2 = s + 2 >= STAGES ? s + 2 - STAGES : s + 2;
            load_stage(kt + 2, s2, m0, o0, sA, sB, tid);
        }
        cp_commit();

        const uint32_t aB = sA + s * A_STAGE;
        const uint32_t bB = sB + s * B_STAGE;
#pragma unroll
        for (int kk = 0; kk < 4; kk++) {
            uint32_t a[4][4], b[4][4];
#pragma unroll
            for (int t = 0; t < 4; t++) {
                int ra = wm * 64 + t * 16 + lr;
                ldsm4(a[t], aB + ra * 128 + (((kk * 2 + lc) ^ (ra & 7)) << 4));
                int rb = wn * 64 + t * 16 + lr;
                ldsm4(b[t], bB + rb * 128 + (((kk * 2 + lc) ^ (rb & 7)) << 4));
            }
#pragma unroll
            for (int mt = 0; mt < 4; mt++)
#pragma unroll
                for (int nt = 0; nt < 8; nt++) {
                    int gidx = nt >> 1, p = nt & 1;
                    mma16816(acc[mt][nt], a[mt], b[gidx][p], b[gidx][p + 2]);
                }
        }
        s = (s + 1 >= STAGES) ? 0 : s + 1;
    }

    // epilogue: direct fp32 stores (bias already folded into K)
#pragma unroll
    for (int mt = 0; mt < 4; mt++) {
        int row0 = m0 + wm * 64 + mt * 16 + (lane >> 2);
#pragma unroll
        for (int nt = 0; nt < 8; nt++) {
            int col = o0 + wn * 64 + nt * 8 + (lane & 3) * 2;
            *reinterpret_cast<float2*>(out + (size_t)row0 * D_OUTV + col) =
                make_float2(acc[mt][nt][0], acc[mt][nt][1]);
            *reinterpret_cast<float2*>(out + (size_t)(row0 + 8) * D_OUTV + col) =
                make_float2(acc[mt][nt][2], acc[mt][nt][3]);
        }
    }
}

// ============================ host launch ============================
extern "C" void kernel_launch(void* const* d_in, const int* in_sizes, int n_in,
                              void* d_out, int out_size) {
    const float* x  = (const float*)d_in[0];
    const float* We = (const float*)d_in[1];
    const float* be = (const float*)d_in[2];
    const float* Wg = (const float*)d_in[3];
    const float* bg = (const float*)d_in[4];
    float* out = (float*)d_out;

    cudaFuncSetAttribute(moe_gemm_kernel,
                         cudaFuncAttributeMaxDynamicSharedMemorySize, SMEM_BYTES);

    gate_kernel<<<N_TOK / 8, 256>>>(x, Wg, bg);
    prescale_kernel<<<N_TOK, 512>>>(x);
    transW_kernel<<<dim3(32, 32, 8), dim3(32, 8)>>>(We);
    biasB_kernel<<<128, 256>>>(be);

    dim3 grid(D_OUTV / BN, N_TOK / BM);   // (4, 64) = 256 blocks
    moe_gemm_kernel<<<grid, THREADS, SMEM_BYTES>>>(out);
}

// round 8
// speedup vs baseline: 2.2845x; 1.0452x over previous
#include <cuda_runtime.h>
#include <cuda_fp16.h>
#include <cstdint>

#define N_TOK 8192
#define D_IN  1024
#define D_OUTV 1024
#define NE    8
#define K_TOT 8192
#define K_PAD 8256            // 8192 + 64 (bias fold + zero pad), 129 * 64

#define BM 128
#define BN 256
#define BK 64
#define STAGES 4
#define NIT (K_PAD / BK)      // 129
#define THREADS 512

#define A_STAGE (BM * BK * 2)         // 16384
#define B_STAGE (BN * BK * 2)         // 32768
#define SMEM_BYTES (STAGES * (A_STAGE + B_STAGE))   // 196608

// ---- scratch (allocation-free device globals) ----
__device__ __align__(1024) __half g_Ah[(size_t)N_TOK * K_PAD];   // A' = gate-scaled x + gate cols
__device__ __align__(1024) __half g_Bh[(size_t)D_OUTV * K_PAD];  // W' [o][k] + bias cols
__device__ float g_gate[N_TOK * NE];

// ============================ PTX helpers ============================
__device__ __forceinline__ uint32_t smem_u32(const void* p) {
    uint32_t a;
    asm("{ .reg .u64 t; cvta.to.shared.u64 t, %1; cvt.u32.u64 %0, t; }" : "=r"(a) : "l"(p));
    return a;
}
__device__ __forceinline__ void cp_async16(uint32_t saddr, const void* gptr) {
    asm volatile("cp.async.cg.shared.global [%0], [%1], 16;\n" :: "r"(saddr), "l"(gptr));
}
__device__ __forceinline__ void cp_commit() {
    asm volatile("cp.async.commit_group;\n");
}
template <int n> __device__ __forceinline__ void cp_wait() {
    asm volatile("cp.async.wait_group %0;\n" :: "n"(n));
}
__device__ __forceinline__ void ldsm4(uint32_t r[4], uint32_t addr) {
    asm volatile("ldmatrix.sync.aligned.m8n8.x4.shared.b16 {%0,%1,%2,%3}, [%4];"
                 : "=r"(r[0]), "=r"(r[1]), "=r"(r[2]), "=r"(r[3]) : "r"(addr));
}
__device__ __forceinline__ void mma16816(float c[4], const uint32_t a[4],
                                         uint32_t b0, uint32_t b1) {
    asm volatile(
        "mma.sync.aligned.m16n8k16.row.col.f32.f16.f16.f32 "
        "{%0,%1,%2,%3}, {%4,%5,%6,%7}, {%8,%9}, {%0,%1,%2,%3};"
        : "+f"(c[0]), "+f"(c[1]), "+f"(c[2]), "+f"(c[3])
        : "r"(a[0]), "r"(a[1]), "r"(a[2]), "r"(a[3]), "r"(b0), "r"(b1));
}

// ============================ prepass kernels ============================
__global__ __launch_bounds__(256) void gate_kernel(const float* __restrict__ x,
                                                   const float* __restrict__ Wg,
                                                   const float* __restrict__ bg) {
    __shared__ float sWg[NE][D_IN];
    int tid = threadIdx.x;
    for (int idx = tid; idx < D_IN * NE; idx += 256) {
        int i = idx >> 3, e = idx & 7;
        sWg[e][i] = Wg[idx];
    }
    __syncthreads();
    int warp = tid >> 5, lane = tid & 31;
    int n = blockIdx.x * 8 + warp;
    const float* xr = x + (size_t)n * D_IN;
    float acc[NE];
#pragma unroll
    for (int e = 0; e < NE; e++) acc[e] = 0.f;
    for (int i = lane; i < D_IN; i += 32) {
        float xv = xr[i];
#pragma unroll
        for (int e = 0; e < NE; e++) acc[e] += xv * sWg[e][i];
    }
#pragma unroll
    for (int e = 0; e < NE; e++)
#pragma unroll
        for (int off = 16; off; off >>= 1)
            acc[e] += __shfl_xor_sync(0xffffffffu, acc[e], off);
    if (lane == 0) {
        float m = -1e30f;
#pragma unroll
        for (int e = 0; e < NE; e++) { acc[e] += bg[e]; m = fmaxf(m, acc[e]); }
        float s = 0.f;
#pragma unroll
        for (int e = 0; e < NE; e++) { acc[e] = expf(acc[e] - m); s += acc[e]; }
        float inv = 1.f / s;
#pragma unroll
        for (int e = 0; e < NE; e++) g_gate[n * NE + e] = acc[e] * inv;
    }
}

// A'[n][e*1024+i] = fp16(g_e * x[n,i]); cols 8192+e = g_e; pad zeros to 8255
__global__ __launch_bounds__(512) void prescale_kernel(const float* __restrict__ x) {
    __shared__ float g[NE];
    int n = blockIdx.x, t = threadIdx.x;
    if (t < NE) g[t] = g_gate[n * NE + t];
    __syncthreads();
    float2 v = reinterpret_cast<const float2*>(x + (size_t)n * D_IN)[t];
    __half* dst = g_Ah + (size_t)n * K_PAD;
#pragma unroll
    for (int e = 0; e < NE; e++) {
        __half2 h = __floats2half2_rn(g[e] * v.x, g[e] * v.y);
        reinterpret_cast<__half2*>(dst + e * D_IN)[t] = h;
    }
    if (t < 32) {   // K extension: 64 cols = 32 half2
        __half2 h = (t < 4) ? __floats2half2_rn(g[2 * t], g[2 * t + 1])
                            : __floats2half2_rn(0.f, 0.f);
        reinterpret_cast<__half2*>(dst + K_TOT)[t] = h;
    }
}

// W'[o][e*1024+i] = fp16(We[e][i][o]) — tiled transpose
__global__ __launch_bounds__(256) void transW_kernel(const float* __restrict__ We) {
    __shared__ float t[32][33];
    int e = blockIdx.z;
    int i0 = blockIdx.y * 32, o0 = blockIdx.x * 32;
    int tx = threadIdx.x, ty = threadIdx.y;
    for (int r = ty; r < 32; r += 8)
        t[r][tx] = We[((size_t)e * D_IN + i0 + r) * D_OUTV + o0 + tx];
    __syncthreads();
    for (int r = ty; r < 32; r += 8)
        g_Bh[(size_t)(o0 + r) * K_PAD + e * D_IN + i0 + tx] = __float2half(t[tx][r]);
}

// B' bias cols: [o][8192+e] = be[e][o], zeros to 8255
__global__ __launch_bounds__(256) void biasB_kernel(const float* __restrict__ be) {
    int idx = blockIdx.x * 256 + threadIdx.x;   // 0 .. 32767
    int o = idx >> 5, j = idx & 31;
    __half2 h = (j < 4) ? __floats2half2_rn(be[(2 * j) * D_OUTV + o],
                                            be[(2 * j + 1) * D_OUTV + o])
                        : __floats2half2_rn(0.f, 0.f);
    reinterpret_cast<__half2*>(g_Bh + (size_t)o * K_PAD + K_TOT)[j] = h;
}

// ============================ main GEMM ============================
__device__ __forceinline__ void load_stage(int kt, int s, int m0, int o0,
                                           uint32_t sA, uint32_t sB, int tid) {
    const int k0 = kt * BK;
#pragma unroll
    for (int j = 0; j < 2; j++) {            // A: 128 rows x 8 chunks = 1024
        int idx = j * 512 + tid;
        int r = idx >> 3, c = idx & 7;
        const void* src = g_Ah + (size_t)(m0 + r) * K_PAD + k0 + c * 8;
        cp_async16(sA + s * A_STAGE + r * 128 + ((c ^ (r & 7)) << 4), src);
    }
#pragma unroll
    for (int j = 0; j < 4; j++) {            // B: 256 rows x 8 chunks = 2048
        int idx = j * 512 + tid;
        int r = idx >> 3, c = idx & 7;
        const void* src = g_Bh + (size_t)(o0 + r) * K_PAD + k0 + c * 8;
        cp_async16(sB + s * B_STAGE + r * 128 + ((c ^ (r & 7)) << 4), src);
    }
}

__global__ __launch_bounds__(THREADS, 1) void moe_gemm_kernel(float* __restrict__ out) {
    extern __shared__ char smem[];
    const uint32_t sA = smem_u32(smem);
    const uint32_t sB = sA + STAGES * A_STAGE;
    const int tid = threadIdx.x, warp = tid >> 5, lane = tid & 31;
    const int wm = warp & 3, wn = warp >> 2;          // 4 (m) x 4 (n) warps
    const int m0 = blockIdx.y * BM;
    const int o0 = blockIdx.x * BN;
    const int lr = lane & 15, lc = lane >> 4;

    float acc[2][8][4];                                // warp tile 32 x 64
#pragma unroll
    for (int mt = 0; mt < 2; mt++)
#pragma unroll
        for (int nt = 0; nt < 8; nt++)
#pragma unroll
            for (int f = 0; f < 4; f++) acc[mt][nt][f] = 0.f;

    load_stage(0, 0, m0, o0, sA, sB, tid); cp_commit();
    load_stage(1, 1, m0, o0, sA, sB, tid); cp_commit();
    load_stage(2, 2, m0, o0, sA, sB, tid); cp_commit();

    int s = 0;
    for (int kt = 0; kt < NIT; kt++) {
        cp_wait<2>();
        __syncthreads();
        if (kt + 3 < NIT) {
            int s3 = s + 3 >= STAGES ? s + 3 - STAGES : s + 3;
            load_stage(kt + 3, s3, m0, o0, sA, sB, tid);
        }
        cp_commit();

        const uint32_t aB = sA + s * A_STAGE;
        const uint32_t bB = sB + s * B_STAGE;
#pragma unroll
        for (int kk = 0; kk < 4; kk++) {
            uint32_t a[2][4], b[4][4];
#pragma unroll
            for (int t = 0; t < 2; t++) {
                int ra = wm * 32 + t * 16 + lr;
                ldsm4(a[t], aB + ra * 128 + (((kk * 2 + lc) ^ (ra & 7)) << 4));
            }
#pragma unroll
            for (int t = 0; t < 4; t++) {
                int rb = wn * 64 + t * 16 + lr;
                ldsm4(b[t], bB + rb * 128 + (((kk * 2 + lc) ^ (rb & 7)) << 4));
            }
#pragma unroll
            for (int mt = 0; mt < 2; mt++)
#pragma unroll
                for (int nt = 0; nt < 8; nt++) {
                    int gidx = nt >> 1, p = nt & 1;
                    mma16816(acc[mt][nt], a[mt], b[gidx][p], b[gidx][p + 2]);
                }
        }
        s = (s + 1 >= STAGES) ? 0 : s + 1;
    }

    // epilogue: direct fp32 stores (bias already folded into K)
#pragma unroll
    for (int mt = 0; mt < 2; mt++) {
        int row0 = m0 + wm * 32 + mt * 16 + (lane >> 2);
#pragma unroll
        for (int nt = 0; nt < 8; nt++) {
            int col = o0 + wn * 64 + nt * 8 + (lane & 3) * 2;
            *reinterpret_cast<float2*>(out + (size_t)row0 * D_OUTV + col) =
                make_float2(acc[mt][nt][0], acc[mt][nt][1]);
            *reinterpret_cast<float2*>(out + (size_t)(row0 + 8) * D_OUTV + col) =
                make_float2(acc[mt][nt][2], acc[mt][nt][3]);
        }
    }
}

// ============================ host launch ============================
extern "C" void kernel_launch(void* const* d_in, const int* in_sizes, int n_in,
                              void* d_out, int out_size) {
    const float* x  = (const float*)d_in[0];
    const float* We = (const float*)d_in[1];
    const float* be = (const float*)d_in[2];
    const float* Wg = (const float*)d_in[3];
    const float* bg = (const float*)d_in[4];
    float* out = (float*)d_out;

    cudaFuncSetAttribute(moe_gemm_kernel,
                         cudaFuncAttributeMaxDynamicSharedMemorySize, SMEM_BYTES);

    gate_kernel<<<N_TOK / 8, 256>>>(x, Wg, bg);
    prescale_kernel<<<N_TOK, 512>>>(x);
    transW_kernel<<<dim3(32, 32, 8), dim3(32, 8)>>>(We);
    biasB_kernel<<<128, 256>>>(be);

    dim3 grid(D_OUTV / BN, N_TOK / BM);   // (4, 64) = 256 blocks
    moe_gemm_kernel<<<grid, THREADS, SMEM_BYTES>>>(out);
}